// round 13
// baseline (speedup 1.0000x reference)
#include <cuda_runtime.h>
#include <cuda_fp16.h>
#include <cstdint>

typedef unsigned long long ull;

constexpr int T_TOK = 16384;
constexpr int H_DIM = 4096;
constexpr int TOPK  = 6;

constexpr int BM     = 64;            // tokens per CTA
constexpr int BK     = 64;            // fp32 K per stage
constexpr int NSTAGE = H_DIM / BK;    // 64
constexpr int NT     = 128;           // 4 warps
constexpr int NCTA   = T_TOK / BM;    // 256 -> 2 CTAs/SM on most SMs

constexpr int XBYTES = BM * BK * 4;       // 16384
constexpr int WBYTES = 64 * BK * 2 * 2;   // 16384 (2 splits, f16)
constexpr int STAGE  = XBYTES + WBYTES;   // 32768
constexpr int DYN    = 2 * STAGE;         // 65536 -> 2 CTAs/SM fit (128K + regs ok)

// static device scratch
__device__ __half   g_W1[64 * H_DIM];
__device__ __half   g_W2[64 * H_DIM];
__device__ float    g_ssum[4][64];
__device__ float    g_cnt [4][64];
__device__ unsigned g_done;

// ---------------------------------------------------------------------------
__device__ __forceinline__ uint32_t smem_u32(const void* p) {
    return (uint32_t)__cvta_generic_to_shared(p);
}
__device__ __forceinline__ void cp16(uint32_t dst, const void* src) {
    asm volatile("cp.async.cg.shared.global [%0], [%1], 16;" :: "r"(dst), "l"(src));
}
__device__ __forceinline__ void ldsm4(uint32_t& r0, uint32_t& r1, uint32_t& r2,
                                      uint32_t& r3, uint32_t a) {
    asm volatile("ldmatrix.sync.aligned.m8n8.x4.shared.b16 {%0,%1,%2,%3}, [%4];"
                 : "=r"(r0), "=r"(r1), "=r"(r2), "=r"(r3) : "r"(a));
}
__device__ __forceinline__ void mma16816(float* c, const uint32_t* a,
                                         uint32_t b0, uint32_t b1) {
    asm volatile(
        "mma.sync.aligned.m16n8k16.row.col.f32.f16.f16.f32 "
        "{%0,%1,%2,%3}, {%4,%5,%6,%7}, {%8,%9}, {%0,%1,%2,%3};"
        : "+f"(c[0]), "+f"(c[1]), "+f"(c[2]), "+f"(c[3])
        : "r"(a[0]), "r"(a[1]), "r"(a[2]), "r"(a[3]), "r"(b0), "r"(b1));
}
__device__ __forceinline__ void split32(float2 v, uint32_t& hi, uint32_t& lo) {
    v.x *= 32.f; v.y *= 32.f;
    __half2 h = __float22half2_rn(v);
    float2 b = __half22float2(h);
    __half2 L = __float22half2_rn(make_float2(v.x - b.x, v.y - b.y));
    hi = *(uint32_t*)&h;
    lo = *(uint32_t*)&L;
}
// X smem: row r x 64 floats (256B), 16B units swizzled by row
__device__ __forceinline__ float2 ldx(const float* xb, int r, int k) {
    int u  = k >> 2;
    int up = (u & 8) | ((u ^ (r & 7)) & 7);
    return *(const float2*)(xb + r * 64 + up * 4 + (k & 3));
}

// ---------------------------------------------------------------------------
// Prep: split W into 2 f16 terms (scaled by 1024), zero accumulators
// ---------------------------------------------------------------------------
__global__ __launch_bounds__(256) void prep_kernel(const float* __restrict__ W) {
    int i = blockIdx.x * 256 + threadIdx.x;    // 65536 float4 chunks
    if (blockIdx.x == 0) {
        ((float*)g_ssum)[threadIdx.x] = 0.f;
        ((float*)g_cnt )[threadIdx.x] = 0.f;
        if (threadIdx.x == 0) g_done = 0u;
    }
    float4 v = ((const float4*)W)[i];
    float a0 = v.x * 1024.f, a1 = v.y * 1024.f, a2 = v.z * 1024.f, a3 = v.w * 1024.f;
    __half2 h01 = __float22half2_rn(make_float2(a0, a1));
    __half2 h23 = __float22half2_rn(make_float2(a2, a3));
    float2 b01 = __half22float2(h01);
    float2 b23 = __half22float2(h23);
    __half2 l01 = __float22half2_rn(make_float2(a0 - b01.x, a1 - b01.y));
    __half2 l23 = __float22half2_rn(make_float2(a2 - b23.x, a3 - b23.y));
    uint2 hw, lw;
    hw.x = *(uint32_t*)&h01; hw.y = *(uint32_t*)&h23;
    lw.x = *(uint32_t*)&l01; lw.y = *(uint32_t*)&l23;
    ((uint2*)g_W1)[i] = hw;
    ((uint2*)g_W2)[i] = lw;
}

// ---------------------------------------------------------------------------
// Fused GEMM (exact R3 structure, BM=64, 2 CTAs/SM) + gating + last-CTA aux
// ---------------------------------------------------------------------------
__global__ __launch_bounds__(NT, 2) void moe_kernel(const float* __restrict__ X,
                                                    float* __restrict__ out) {
    extern __shared__ char dsm[];
    __shared__ float s_red[2][64];
    __shared__ float s_cnt[64];
    __shared__ int   s_last;

    const int tid  = threadIdx.x;
    const int w    = tid >> 5;
    const int l    = tid & 31;
    const int tile = blockIdx.x;
    const float* Xt = X + (size_t)tile * BM * H_DIM;

    if (tid < 64) s_cnt[tid] = 0.f;

    // stage loader (cp.async, double buffered) — R3 structure
    auto cp_stage = [&](int s) {
        const int k0 = s * BK;
        const uint32_t xb = smem_u32(dsm) + (s & 1) * STAGE;
        const uint32_t wb = xb + XBYTES;
        #pragma unroll
        for (int i = 0; i < 8; i++) {                 // 64 rows x 16 units
            int ch = tid + i * NT;
            int r = ch >> 4, u = ch & 15;
            int up = (u & 8) | ((u ^ (r & 7)) & 7);
            cp16(xb + r * 256 + up * 16, Xt + (size_t)r * H_DIM + k0 + u * 4);
        }
        #pragma unroll
        for (int i = 0; i < 8; i++) {                 // 64 experts x 16 units
            int ch = tid + i * NT;
            int e = ch >> 4, u = ch & 15;
            int split = u >> 3, kk = u & 7;
            int up = (u & 8) | ((u ^ (e & 7)) & 7);
            const __half* src = (split ? g_W2 : g_W1) + e * H_DIM + k0 + kk * 8;
            cp16(wb + e * 256 + up * 16, src);
        }
        asm volatile("cp.async.commit_group;");
    };

    float acc[8][4];
    #pragma unroll
    for (int i = 0; i < 8; i++)
        #pragma unroll
        for (int j = 0; j < 4; j++) acc[i][j] = 0.f;

    // R3 lane constants: warp = 16 tokens x 64 experts
    const int t8     = l >> 3;
    const int e_base = (t8 >> 1) * 8 + (l & 7);
    const int koff   = t8 & 1;
    const int c7     = e_base & 7;

    cp_stage(0);

    for (int s = 0; s < NSTAGE; s++) {
        if (s + 1 < NSTAGE) {
            cp_stage(s + 1);
            asm volatile("cp.async.wait_group 1;");
        } else {
            asm volatile("cp.async.wait_group 0;");
        }
        __syncthreads();

        const char* sb = dsm + (s & 1) * STAGE;
        const float* xb = (const float*)sb;
        const uint32_t wbe = smem_u32(sb + XBYTES) + e_base * 256;
        const int r0 = w * 16 + (l >> 2);
        const int r1 = r0 + 8;

        #pragma unroll
        for (int c16 = 0; c16 < 4; c16++) {
            const int kA = c16 * 16 + (l & 3) * 2;
            uint32_t ahi[4], alo[4];
            split32(ldx(xb, r0, kA),     ahi[0], alo[0]);
            split32(ldx(xb, r1, kA),     ahi[1], alo[1]);
            split32(ldx(xb, r0, kA + 8), ahi[2], alo[2]);
            split32(ldx(xb, r1, kA + 8), ahi[3], alo[3]);

            const int u0  = c16 * 2 + koff;
            const int uph = (u0 ^ c7) & 7;
            #pragma unroll
            for (int pe = 0; pe < 4; pe++) {
                uint32_t ah = wbe + pe * 4096 + uph * 16;  // split-hi units 0..7
                uint32_t bh0, bh1, bh2, bh3, bl0, bl1, bl2, bl3;
                ldsm4(bh0, bh1, bh2, bh3, ah);
                ldsm4(bl0, bl1, bl2, bl3, ah + 128);       // split-lo units 8..15
                mma16816(acc[2 * pe],     ahi, bh0, bh1);
                mma16816(acc[2 * pe],     ahi, bl0, bl1);
                mma16816(acc[2 * pe],     alo, bh0, bh1);
                mma16816(acc[2 * pe + 1], ahi, bh2, bh3);
                mma16816(acc[2 * pe + 1], ahi, bl2, bl3);
                mma16816(acc[2 * pe + 1], alo, bh2, bh3);
            }
        }
        __syncthreads();
    }

    // ---------------- epilogue: scores to smem [64][65] ----------------
    float* S = (float*)dsm;
    {
        const int r0 = w * 16 + (l >> 2);
        const int c0 = (l & 3) * 2;
        constexpr float INV = 1.0f / 32768.0f;
        #pragma unroll
        for (int eb = 0; eb < 8; eb++) {
            S[r0 * 65 + eb * 8 + c0]           = acc[eb][0] * INV;
            S[r0 * 65 + eb * 8 + c0 + 1]       = acc[eb][1] * INV;
            S[(r0 + 8) * 65 + eb * 8 + c0]     = acc[eb][2] * INV;
            S[(r0 + 8) * 65 + eb * 8 + c0 + 1] = acc[eb][3] * INV;
        }
    }
    __syncthreads();

    if (tid < 64) {
        float sc[64];
        #pragma unroll
        for (int e = 0; e < 64; e++) sc[e] = S[tid * 65 + e];

        // softmax
        float m = sc[0];
        #pragma unroll
        for (int e = 1; e < 64; e++) m = fmaxf(m, sc[e]);
        float ssum = 0.f;
        #pragma unroll
        for (int e = 0; e < 64; e++) { sc[e] = expf(sc[e] - m); ssum += sc[e]; }
        float inv = 1.0f / ssum;
        #pragma unroll
        for (int e = 0; e < 64; e++) sc[e] *= inv;

        // group maxima
        float gm[8];
        #pragma unroll
        for (int g = 0; g < 8; g++) {
            float a = sc[g * 8];
            #pragma unroll
            for (int j = 1; j < 8; j++) a = fmaxf(a, sc[g * 8 + j]);
            gm[g] = a;
        }
        // top-3 groups
        unsigned keep = 0;
        #pragma unroll
        for (int r = 0; r < 3; r++) {
            float bv = -1.f; int bi = 0;
            #pragma unroll
            for (int g = 0; g < 8; g++) {
                bool ok = !((keep >> g) & 1) && (gm[g] > bv);
                if (ok) { bv = gm[g]; bi = g; }
            }
            keep |= 1u << bi;
        }
        // top-6 experts in kept groups
        ull picked = 0;
        float wsum = 0.f;
        int idxs[6]; float vals[6];
        #pragma unroll
        for (int r = 0; r < 6; r++) {
            float bv = -1.f; int bi = 0;
            #pragma unroll
            for (int e = 0; e < 64; e++) {
                bool ok = ((keep >> (e >> 3)) & 1) && !((picked >> e) & 1) && (sc[e] > bv);
                if (ok) { bv = sc[e]; bi = e; }
            }
            picked |= 1ull << bi;
            idxs[r] = bi; vals[r] = bv; wsum += bv;
        }
        float inv2 = 1.0f / (wsum + 1e-20f);

        const int t = tile * BM + tid;
        #pragma unroll
        for (int r = 0; r < 6; r++) {
            out[t * TOPK + r]                = (float)idxs[r];
            out[T_TOK * TOPK + t * TOPK + r] = vals[r] * inv2;
        }

        // aux accumulators (64-token tiles never straddle batches)
        #pragma unroll
        for (int e = 0; e < 64; e++) {
            float v = sc[e];
            #pragma unroll
            for (int d = 16; d > 0; d >>= 1) v += __shfl_xor_sync(0xffffffffu, v, d);
            if (l == 0) s_red[w][e] = v;
        }
        #pragma unroll
        for (int r = 0; r < 6; r++) atomicAdd(&s_cnt[idxs[r]], 1.0f);
    }
    __syncthreads();
    if (tid < 64) {
        float a = s_red[0][tid] + s_red[1][tid];
        const int b = (tile * BM) >> 12;
        atomicAdd(&g_ssum[b][tid], a);
        atomicAdd(&g_cnt [b][tid], s_cnt[tid]);
    }
    __threadfence();
    __syncthreads();
    if (tid == 0) {
        unsigned o = atomicAdd(&g_done, 1u);
        s_last = (o == NCTA - 1);
    }
    __syncthreads();
    if (s_last && w == 0) {
        __threadfence();
        float a = 0.f;
        #pragma unroll
        for (int i = 0; i < 8; i++) {
            int j = l * 8 + i;
            a += __ldcg(&((const float*)g_cnt)[j]) * __ldcg(&((const float*)g_ssum)[j]);
        }
        #pragma unroll
        for (int d = 16; d > 0; d >>= 1) a += __shfl_xor_sync(0xffffffffu, a, d);
        if (l == 0)
            out[2 * T_TOK * TOPK] = a * (0.001f / (4.0f * 384.0f * 4096.0f));
    }
}

extern "C" void kernel_launch(void* const* d_in, const int* in_sizes, int n_in,
                              void* d_out, int out_size) {
    const float* X = (const float*)d_in[0];   // [4,4096,4096] fp32
    const float* W = (const float*)d_in[1];   // [64,4096] fp32
    float* out = (float*)d_out;

    cudaFuncSetAttribute(moe_kernel, cudaFuncAttributeMaxDynamicSharedMemorySize, DYN);
    prep_kernel<<<256, 256>>>(W);
    moe_kernel<<<NCTA, NT, DYN>>>(X, out);
}

// round 14
// speedup vs baseline: 1.5200x; 1.5200x over previous
#include <cuda_runtime.h>
#include <cuda_fp16.h>
#include <cstdint>

typedef unsigned long long ull;

constexpr int T_TOK = 16384;
constexpr int H_DIM = 4096;
constexpr int TOPK  = 6;

constexpr int BM     = 128;           // tokens per CTA
constexpr int BK     = 64;            // fp32 K per stage
constexpr int NSTAGE = H_DIM / BK;    // 64
constexpr int NT     = 256;           // 8 warps
constexpr int NCTA   = T_TOK / BM;    // 128

constexpr int XBYTES = BM * BK * 4;       // 32768
constexpr int WBYTES = 64 * BK * 2 * 2;   // 16384 (2 splits, f16)
constexpr int STAGE  = XBYTES + WBYTES;   // 49152
constexpr int DYN    = 2 * STAGE;         // 98304

// static device scratch
__device__ __half   g_W1[64 * H_DIM];
__device__ __half   g_W2[64 * H_DIM];
__device__ float    g_ssum[4][64];
__device__ float    g_cnt [4][64];
__device__ unsigned g_done;

// ---------------------------------------------------------------------------
__device__ __forceinline__ uint32_t smem_u32(const void* p) {
    return (uint32_t)__cvta_generic_to_shared(p);
}
__device__ __forceinline__ void cp16(uint32_t dst, const void* src) {
    asm volatile("cp.async.cg.shared.global [%0], [%1], 16;" :: "r"(dst), "l"(src));
}
__device__ __forceinline__ void ldsm4(uint32_t& r0, uint32_t& r1, uint32_t& r2,
                                      uint32_t& r3, uint32_t a) {
    asm volatile("ldmatrix.sync.aligned.m8n8.x4.shared.b16 {%0,%1,%2,%3}, [%4];"
                 : "=r"(r0), "=r"(r1), "=r"(r2), "=r"(r3) : "r"(a));
}
__device__ __forceinline__ void mma16816(float* c, const uint32_t* a,
                                         uint32_t b0, uint32_t b1) {
    asm volatile(
        "mma.sync.aligned.m16n8k16.row.col.f32.f16.f16.f32 "
        "{%0,%1,%2,%3}, {%4,%5,%6,%7}, {%8,%9}, {%0,%1,%2,%3};"
        : "+f"(c[0]), "+f"(c[1]), "+f"(c[2]), "+f"(c[3])
        : "r"(a[0]), "r"(a[1]), "r"(a[2]), "r"(a[3]), "r"(b0), "r"(b1));
}
__device__ __forceinline__ void split32(float2 v, uint32_t& hi, uint32_t& lo) {
    v.x *= 32.f; v.y *= 32.f;
    __half2 h = __float22half2_rn(v);
    float2 b = __half22float2(h);
    __half2 L = __float22half2_rn(make_float2(v.x - b.x, v.y - b.y));
    hi = *(uint32_t*)&h;
    lo = *(uint32_t*)&L;
}
// X smem: row r (0..127) x 64 floats, 16B-unit swizzled: u' = (u&8)|((u^(r&7))&7)
__device__ __forceinline__ float2 ldx(const float* xb, int r, int k) {
    int u  = k >> 2;
    int up = (u & 8) | ((u ^ (r & 7)) & 7);
    return *(const float2*)(xb + r * 64 + up * 4 + (k & 3));
}

// ---------------------------------------------------------------------------
// Prep: split W into 2 f16 terms (scaled by 1024), zero accumulators
// ---------------------------------------------------------------------------
__global__ __launch_bounds__(256) void prep_kernel(const float* __restrict__ W) {
    int i = blockIdx.x * 256 + threadIdx.x;    // 65536 float4 chunks
    if (blockIdx.x == 0) {
        ((float*)g_ssum)[threadIdx.x] = 0.f;
        ((float*)g_cnt )[threadIdx.x] = 0.f;
        if (threadIdx.x == 0) g_done = 0u;
    }
    float4 v = ((const float4*)W)[i];
    float a0 = v.x * 1024.f, a1 = v.y * 1024.f, a2 = v.z * 1024.f, a3 = v.w * 1024.f;
    __half2 h01 = __float22half2_rn(make_float2(a0, a1));
    __half2 h23 = __float22half2_rn(make_float2(a2, a3));
    float2 b01 = __half22float2(h01);
    float2 b23 = __half22float2(h23);
    __half2 l01 = __float22half2_rn(make_float2(a0 - b01.x, a1 - b01.y));
    __half2 l23 = __float22half2_rn(make_float2(a2 - b23.x, a3 - b23.y));
    uint2 hw, lw;
    hw.x = *(uint32_t*)&h01; hw.y = *(uint32_t*)&h23;
    lw.x = *(uint32_t*)&l01; lw.y = *(uint32_t*)&l23;
    ((uint2*)g_W1)[i] = hw;
    ((uint2*)g_W2)[i] = lw;
}

// ---------------------------------------------------------------------------
// Fused GEMM (exact R3 kernel) + gating epilogue + last-CTA aux loss
// ---------------------------------------------------------------------------
__global__ __launch_bounds__(NT, 1) void moe_kernel(const float* __restrict__ X,
                                                    float* __restrict__ out) {
    extern __shared__ char dsm[];
    __shared__ float s_red[4][64];
    __shared__ float s_cnt[64];
    __shared__ int   s_last;

    const int tid  = threadIdx.x;
    const int w    = tid >> 5;
    const int l    = tid & 31;
    const int tile = blockIdx.x;
    const float* Xt = X + (size_t)tile * BM * H_DIM;

    if (tid < 64) s_cnt[tid] = 0.f;

    // stage loader (cp.async) — R3 verbatim
    auto load_stage = [&](int s) {
        const int k0 = s * BK;
        const uint32_t xb = smem_u32(dsm) + (s & 1) * STAGE;
        const uint32_t wb = xb + XBYTES;
        #pragma unroll
        for (int i = 0; i < 8; i++) {
            int ch = tid + i * NT;
            int r = ch >> 4, u = ch & 15;
            int up = (u & 8) | ((u ^ (r & 7)) & 7);
            cp16(xb + r * 256 + up * 16, Xt + (size_t)r * H_DIM + k0 + u * 4);
        }
        #pragma unroll
        for (int i = 0; i < 4; i++) {
            int ch = tid + i * NT;
            int e = ch >> 4, u = ch & 15;
            int split = u >> 3, kk = u & 7;
            int up = (u & 8) | ((u ^ (e & 7)) & 7);
            const __half* src = (split ? g_W2 : g_W1) + e * H_DIM + k0 + kk * 8;
            cp16(wb + e * 256 + up * 16, src);
        }
        asm volatile("cp.async.commit_group;");
    };

    float acc[8][4];
    #pragma unroll
    for (int i = 0; i < 8; i++)
        #pragma unroll
        for (int j = 0; j < 4; j++) acc[i][j] = 0.f;

    // R3 lane constants: warp = 16 tokens x 64 experts
    const int t8     = l >> 3;
    const int e_base = (t8 >> 1) * 8 + (l & 7);
    const int koff   = t8 & 1;
    const int c7     = e_base & 7;

    load_stage(0);

    for (int s = 0; s < NSTAGE; s++) {
        if (s + 1 < NSTAGE) {
            load_stage(s + 1);
            asm volatile("cp.async.wait_group 1;");
        } else {
            asm volatile("cp.async.wait_group 0;");
        }
        __syncthreads();

        const char* sb = dsm + (s & 1) * STAGE;
        const float* xb = (const float*)sb;
        const uint32_t wbe = smem_u32(sb + XBYTES) + e_base * 256;
        const int r0 = w * 16 + (l >> 2);
        const int r1 = r0 + 8;

        #pragma unroll
        for (int c16 = 0; c16 < 4; c16++) {
            const int kA = c16 * 16 + (l & 3) * 2;
            uint32_t ahi[4], alo[4];
            split32(ldx(xb, r0, kA),     ahi[0], alo[0]);
            split32(ldx(xb, r1, kA),     ahi[1], alo[1]);
            split32(ldx(xb, r0, kA + 8), ahi[2], alo[2]);
            split32(ldx(xb, r1, kA + 8), ahi[3], alo[3]);

            const int u0  = c16 * 2 + koff;
            const int uph = (u0 ^ c7) & 7;
            #pragma unroll
            for (int pe = 0; pe < 4; pe++) {
                uint32_t ah = wbe + pe * 4096 + uph * 16;  // split-hi units 0..7
                uint32_t bh0, bh1, bh2, bh3, bl0, bl1, bl2, bl3;
                ldsm4(bh0, bh1, bh2, bh3, ah);
                ldsm4(bl0, bl1, bl2, bl3, ah + 128);       // split-lo units 8..15
                mma16816(acc[2 * pe],     ahi, bh0, bh1);
                mma16816(acc[2 * pe],     ahi, bl0, bl1);
                mma16816(acc[2 * pe],     alo, bh0, bh1);
                mma16816(acc[2 * pe + 1], ahi, bh2, bh3);
                mma16816(acc[2 * pe + 1], ahi, bl2, bl3);
                mma16816(acc[2 * pe + 1], alo, bh2, bh3);
            }
        }
        __syncthreads();
    }

    // ---------------- epilogue: transpose scores to smem ----------------
    float* S = (float*)dsm;               // [128][65]
    {
        const int r0 = w * 16 + (l >> 2);
        const int c0 = (l & 3) * 2;
        constexpr float INV = 1.0f / 32768.0f;
        #pragma unroll
        for (int eb = 0; eb < 8; eb++) {
            S[r0 * 65 + eb * 8 + c0]           = acc[eb][0] * INV;
            S[r0 * 65 + eb * 8 + c0 + 1]       = acc[eb][1] * INV;
            S[(r0 + 8) * 65 + eb * 8 + c0]     = acc[eb][2] * INV;
            S[(r0 + 8) * 65 + eb * 8 + c0 + 1] = acc[eb][3] * INV;
        }
    }
    __syncthreads();

    if (tid < 128) {
        float sc[64];
        #pragma unroll
        for (int e = 0; e < 64; e++) sc[e] = S[tid * 65 + e];

        // softmax
        float m = sc[0];
        #pragma unroll
        for (int e = 1; e < 64; e++) m = fmaxf(m, sc[e]);
        float ssum = 0.f;
        #pragma unroll
        for (int e = 0; e < 64; e++) { sc[e] = expf(sc[e] - m); ssum += sc[e]; }
        float inv = 1.0f / ssum;
        #pragma unroll
        for (int e = 0; e < 64; e++) sc[e] *= inv;

        // group maxima
        float gm[8];
        #pragma unroll
        for (int g = 0; g < 8; g++) {
            float a = sc[g * 8];
            #pragma unroll
            for (int j = 1; j < 8; j++) a = fmaxf(a, sc[g * 8 + j]);
            gm[g] = a;
        }
        // top-3 groups
        unsigned keep = 0;
        #pragma unroll
        for (int r = 0; r < 3; r++) {
            float bv = -1.f; int bi = 0;
            #pragma unroll
            for (int g = 0; g < 8; g++) {
                bool ok = !((keep >> g) & 1) && (gm[g] > bv);
                if (ok) { bv = gm[g]; bi = g; }
            }
            keep |= 1u << bi;
        }
        // top-6 experts in kept groups
        ull picked = 0;
        float wsum = 0.f;
        int idxs[6]; float vals[6];
        #pragma unroll
        for (int r = 0; r < 6; r++) {
            float bv = -1.f; int bi = 0;
            #pragma unroll
            for (int e = 0; e < 64; e++) {
                bool ok = ((keep >> (e >> 3)) & 1) && !((picked >> e) & 1) && (sc[e] > bv);
                if (ok) { bv = sc[e]; bi = e; }
            }
            picked |= 1ull << bi;
            idxs[r] = bi; vals[r] = bv; wsum += bv;
        }
        float inv2 = 1.0f / (wsum + 1e-20f);

        const int t = tile * BM + tid;
        #pragma unroll
        for (int r = 0; r < 6; r++) {
            out[t * TOPK + r]                = (float)idxs[r];
            out[T_TOK * TOPK + t * TOPK + r] = vals[r] * inv2;
        }

        // aux accumulators (128-token tiles never straddle batches)
        #pragma unroll
        for (int e = 0; e < 64; e++) {
            float v = sc[e];
            v += __shfl_xor_sync(0xffffffffu, v, 16);
            v += __shfl_xor_sync(0xffffffffu, v, 8);
            v += __shfl_xor_sync(0xffffffffu, v, 4);
            v += __shfl_xor_sync(0xffffffffu, v, 2);
            v += __shfl_xor_sync(0xffffffffu, v, 1);
            if (l == 0) s_red[w][e] = v;
        }
        #pragma unroll
        for (int r = 0; r < 6; r++) atomicAdd(&s_cnt[idxs[r]], 1.0f);
    }
    __syncthreads();
    if (tid < 64) {
        float a = s_red[0][tid] + s_red[1][tid] + s_red[2][tid] + s_red[3][tid];
        const int b = (tile * BM) >> 12;
        atomicAdd(&g_ssum[b][tid], a);
        atomicAdd(&g_cnt [b][tid], s_cnt[tid]);
    }
    __threadfence();
    __syncthreads();
    if (tid == 0) {
        unsigned o = atomicAdd(&g_done, 1u);
        s_last = (o == NCTA - 1);
    }
    __syncthreads();
    if (s_last && w == 0) {
        __threadfence();
        float a = 0.f;
        #pragma unroll
        for (int i = 0; i < 8; i++) {
            int j = l * 8 + i;
            a += __ldcg(&((const float*)g_cnt)[j]) * __ldcg(&((const float*)g_ssum)[j]);
        }
        #pragma unroll
        for (int d = 16; d > 0; d >>= 1) a += __shfl_xor_sync(0xffffffffu, a, d);
        if (l == 0)
            out[2 * T_TOK * TOPK] = a * (0.001f / (4.0f * 384.0f * 4096.0f));
    }
}

extern "C" void kernel_launch(void* const* d_in, const int* in_sizes, int n_in,
                              void* d_out, int out_size) {
    const float* X = (const float*)d_in[0];   // [4,4096,4096] fp32
    const float* W = (const float*)d_in[1];   // [64,4096] fp32
    float* out = (float*)d_out;

    cudaFuncSetAttribute(moe_kernel, cudaFuncAttributeMaxDynamicSharedMemorySize, DYN);
    prep_kernel<<<256, 256>>>(W);
    moe_kernel<<<NCTA, NT, DYN>>>(X, out);
}

// round 16
// speedup vs baseline: 1.7479x; 1.1499x over previous
#include <cuda_runtime.h>
#include <cuda_fp16.h>
#include <cstdint>

typedef unsigned long long ull;

constexpr int T_TOK = 16384;
constexpr int H_DIM = 4096;
constexpr int N_E   = 64;
constexpr int TOPK  = 6;
constexpr int S_SEQ = 4096;

constexpr int BM     = 128;           // tokens per CTA
constexpr int BK     = 64;            // fp32 K per stage
constexpr int NSTAGE = H_DIM / BK;    // 64
constexpr int NT     = 512;           // 16 warps: 8 row-groups x 2 k-halves

constexpr int XBYTES = BM * BK * 4;       // 32768
constexpr int WBYTES = N_E * BK * 2 * 2;  // 16384 (2 splits, f16)
constexpr int STAGE  = XBYTES + WBYTES;   // 49152
constexpr int DYN    = 2 * STAGE;         // 98304

constexpr int SBYTES = 128 * 65 * 4;      // 33280, two buffers fit in DYN

// static device scratch
__device__ __half g_W1[N_E * H_DIM];
__device__ __half g_W2[N_E * H_DIM];
__device__ float  g_ssum[4][64];
__device__ float  g_cnt [4][64];

// ---------------------------------------------------------------------------
__device__ __forceinline__ uint32_t smem_u32(const void* p) {
    return (uint32_t)__cvta_generic_to_shared(p);
}
__device__ __forceinline__ void cp16(uint32_t dst, const void* src) {
    asm volatile("cp.async.cg.shared.global [%0], [%1], 16;" :: "r"(dst), "l"(src));
}
__device__ __forceinline__ void ldsm4(uint32_t& r0, uint32_t& r1, uint32_t& r2,
                                      uint32_t& r3, uint32_t a) {
    asm volatile("ldmatrix.sync.aligned.m8n8.x4.shared.b16 {%0,%1,%2,%3}, [%4];"
                 : "=r"(r0), "=r"(r1), "=r"(r2), "=r"(r3) : "r"(a));
}
__device__ __forceinline__ void mma16816(float* c, const uint32_t* a,
                                         uint32_t b0, uint32_t b1) {
    asm volatile(
        "mma.sync.aligned.m16n8k16.row.col.f32.f16.f16.f32 "
        "{%0,%1,%2,%3}, {%4,%5,%6,%7}, {%8,%9}, {%0,%1,%2,%3};"
        : "+f"(c[0]), "+f"(c[1]), "+f"(c[2]), "+f"(c[3])
        : "r"(a[0]), "r"(a[1]), "r"(a[2]), "r"(a[3]), "r"(b0), "r"(b1));
}
__device__ __forceinline__ void split32(float2 v, uint32_t& hi, uint32_t& lo) {
    v.x *= 32.f; v.y *= 32.f;
    __half2 h = __float22half2_rn(v);
    float2 b = __half22float2(h);
    __half2 L = __float22half2_rn(make_float2(v.x - b.x, v.y - b.y));
    hi = *(uint32_t*)&h;
    lo = *(uint32_t*)&L;
}
// X smem: row r (0..127) x 64 floats, 16B-unit swizzled: u' = (u&8)|((u^(r&7))&7)
__device__ __forceinline__ float2 ldx(const float* xb, int r, int k) {
    int u  = k >> 2;
    int up = (u & 8) | ((u ^ (r & 7)) & 7);
    return *(const float2*)(xb + r * 64 + up * 4 + (k & 3));
}

// ---------------------------------------------------------------------------
// Prep: split W into 2 f16 terms (scaled by 1024), zero aux accumulators
// ---------------------------------------------------------------------------
__global__ __launch_bounds__(256) void prep_kernel(const float* __restrict__ W) {
    int idx = blockIdx.x * 256 + threadIdx.x;
    if (blockIdx.x == 0) {
        ((float*)g_ssum)[threadIdx.x] = 0.f;
        ((float*)g_cnt )[threadIdx.x] = 0.f;
    }
    #pragma unroll
    for (int r = 0; r < 4; r++) {
        int i = idx + r * 16384;              // float4 index, 65536 total
        float4 v = ((const float4*)W)[i];
        float a0 = v.x * 1024.f, a1 = v.y * 1024.f, a2 = v.z * 1024.f, a3 = v.w * 1024.f;
        __half2 h01 = __float22half2_rn(make_float2(a0, a1));
        __half2 h23 = __float22half2_rn(make_float2(a2, a3));
        float2 b01 = __half22float2(h01);
        float2 b23 = __half22float2(h23);
        __half2 l01 = __float22half2_rn(make_float2(a0 - b01.x, a1 - b01.y));
        __half2 l23 = __float22half2_rn(make_float2(a2 - b23.x, a3 - b23.y));
        uint2 hw, lw;
        hw.x = *(uint32_t*)&h01; hw.y = *(uint32_t*)&h23;
        lw.x = *(uint32_t*)&l01; lw.y = *(uint32_t*)&l23;
        ((uint2*)g_W1)[i] = hw;
        ((uint2*)g_W2)[i] = lw;
    }
}

// ---------------------------------------------------------------------------
// Fused GEMM (R3 mapping, k-split across warp pairs) + gating epilogue
// ---------------------------------------------------------------------------
__global__ __launch_bounds__(NT, 1) void moe_kernel(const float* __restrict__ X,
                                                    float* __restrict__ out) {
    extern __shared__ char dsm[];
    __shared__ float s_red[4][64];
    __shared__ float s_cnt[64];

    const int tid  = threadIdx.x;
    const int w    = tid >> 5;
    const int l    = tid & 31;
    const int tile = blockIdx.x;
    const float* Xt = X + (size_t)tile * BM * H_DIM;

    if (tid < 64) s_cnt[tid] = 0.f;

    // stage loader (cp.async) — R3 pattern, 512 threads
    auto load_stage = [&](int s) {
        const int k0 = s * BK;
        const uint32_t xb = smem_u32(dsm) + (s & 1) * STAGE;
        const uint32_t wb = xb + XBYTES;
        #pragma unroll
        for (int i = 0; i < 4; i++) {                 // 128 rows x 16 units
            int ch = tid + i * NT;
            int r = ch >> 4, u = ch & 15;
            int up = (u & 8) | ((u ^ (r & 7)) & 7);
            cp16(xb + r * 256 + up * 16, Xt + (size_t)r * H_DIM + k0 + u * 4);
        }
        #pragma unroll
        for (int i = 0; i < 2; i++) {                 // 64 experts x 16 units
            int ch = tid + i * NT;
            int e = ch >> 4, u = ch & 15;
            int split = u >> 3, kk = u & 7;
            int up = (u & 8) | ((u ^ (e & 7)) & 7);
            const __half* src = (split ? g_W2 : g_W1) + e * H_DIM + k0 + kk * 8;
            cp16(wb + e * 256 + up * 16, src);
        }
        asm volatile("cp.async.commit_group;");
    };

    float acc[8][4];
    #pragma unroll
    for (int i = 0; i < 8; i++)
        #pragma unroll
        for (int j = 0; j < 4; j++) acc[i][j] = 0.f;

    // warp pair: wr = row group (16 tokens), kh = k half (c16 pair)
    const int wr = w & 7;
    const int kh = w >> 3;
    // R3 lane constants: warp covers all 64 experts
    const int t8     = l >> 3;
    const int e_base = (t8 >> 1) * 8 + (l & 7);
    const int koff   = t8 & 1;
    const int c7     = e_base & 7;

    load_stage(0);

    for (int s = 0; s < NSTAGE; s++) {
        if (s + 1 < NSTAGE) {
            load_stage(s + 1);
            asm volatile("cp.async.wait_group 1;");
        } else {
            asm volatile("cp.async.wait_group 0;");
        }
        __syncthreads();

        const char* sb = dsm + (s & 1) * STAGE;
        const float* xb = (const float*)sb;
        const uint32_t wbe = smem_u32(sb + XBYTES) + e_base * 256;
        const int r0 = wr * 16 + (l >> 2);
        const int r1 = r0 + 8;

        #pragma unroll
        for (int cc = 0; cc < 2; cc++) {
            const int c16 = kh * 2 + cc;
            const int kA = c16 * 16 + (l & 3) * 2;
            uint32_t ahi[4], alo[4];
            split32(ldx(xb, r0, kA),     ahi[0], alo[0]);
            split32(ldx(xb, r1, kA),     ahi[1], alo[1]);
            split32(ldx(xb, r0, kA + 8), ahi[2], alo[2]);
            split32(ldx(xb, r1, kA + 8), ahi[3], alo[3]);

            const int u0  = c16 * 2 + koff;
            const int uph = (u0 ^ c7) & 7;
            #pragma unroll
            for (int pe = 0; pe < 4; pe++) {
                uint32_t ah = wbe + pe * 4096 + uph * 16;  // split-hi units 0..7
                uint32_t bh0, bh1, bh2, bh3, bl0, bl1, bl2, bl3;
                ldsm4(bh0, bh1, bh2, bh3, ah);
                ldsm4(bl0, bl1, bl2, bl3, ah + 128);       // split-lo units 8..15
                mma16816(acc[2 * pe],     ahi, bh0, bh1);
                mma16816(acc[2 * pe],     ahi, bl0, bl1);
                mma16816(acc[2 * pe],     alo, bh0, bh1);
                mma16816(acc[2 * pe + 1], ahi, bh2, bh3);
                mma16816(acc[2 * pe + 1], ahi, bl2, bl3);
                mma16816(acc[2 * pe + 1], alo, bh2, bh3);
            }
        }
        __syncthreads();
    }

    // ------- epilogue: two k-half score buffers, then merge -------
    float* S = (float*)(dsm + kh * SBYTES);   // [128][65] per k-half
    {
        const int r0 = wr * 16 + (l >> 2);
        const int c0 = (l & 3) * 2;
        constexpr float INV = 1.0f / 32768.0f;
        #pragma unroll
        for (int eb = 0; eb < 8; eb++) {
            S[r0 * 65 + eb * 8 + c0]           = acc[eb][0] * INV;
            S[r0 * 65 + eb * 8 + c0 + 1]       = acc[eb][1] * INV;
            S[(r0 + 8) * 65 + eb * 8 + c0]     = acc[eb][2] * INV;
            S[(r0 + 8) * 65 + eb * 8 + c0 + 1] = acc[eb][3] * INV;
        }
    }
    __syncthreads();

    if (tid < 128) {
        const float* S0 = (const float*)dsm;
        const float* S1 = (const float*)(dsm + SBYTES);
        float sc[64];
        #pragma unroll
        for (int e = 0; e < 64; e++) sc[e] = S0[tid * 65 + e] + S1[tid * 65 + e];

        // softmax
        float m = sc[0];
        #pragma unroll
        for (int e = 1; e < 64; e++) m = fmaxf(m, sc[e]);
        float ssum = 0.f;
        #pragma unroll
        for (int e = 0; e < 64; e++) { sc[e] = expf(sc[e] - m); ssum += sc[e]; }
        float inv = 1.0f / ssum;
        #pragma unroll
        for (int e = 0; e < 64; e++) sc[e] *= inv;

        // group maxima
        float gm[8];
        #pragma unroll
        for (int g = 0; g < 8; g++) {
            float a = sc[g * 8];
            #pragma unroll
            for (int j = 1; j < 8; j++) a = fmaxf(a, sc[g * 8 + j]);
            gm[g] = a;
        }
        // top-3 groups
        unsigned keep = 0;
        #pragma unroll
        for (int r = 0; r < 3; r++) {
            float bv = -1.f; int bi = 0;
            #pragma unroll
            for (int g = 0; g < 8; g++) {
                bool ok = !((keep >> g) & 1) && (gm[g] > bv);
                if (ok) { bv = gm[g]; bi = g; }
            }
            keep |= 1u << bi;
        }
        // top-6 experts in kept groups
        ull picked = 0;
        float wsum = 0.f;
        int idxs[6]; float vals[6];
        #pragma unroll
        for (int r = 0; r < 6; r++) {
            float bv = -1.f; int bi = 0;
            #pragma unroll
            for (int e = 0; e < 64; e++) {
                bool ok = ((keep >> (e >> 3)) & 1) && !((picked >> e) & 1) && (sc[e] > bv);
                if (ok) { bv = sc[e]; bi = e; }
            }
            picked |= 1ull << bi;
            idxs[r] = bi; vals[r] = bv; wsum += bv;
        }
        float inv2 = 1.0f / (wsum + 1e-20f);

        const int t = tile * BM + tid;
        #pragma unroll
        for (int r = 0; r < 6; r++) {
            out[t * TOPK + r]                = (float)idxs[r];
            out[T_TOK * TOPK + t * TOPK + r] = vals[r] * inv2;
        }

        // aux accumulators
        #pragma unroll
        for (int e = 0; e < 64; e++) {
            float v = sc[e];
            v += __shfl_xor_sync(0xffffffffu, v, 16);
            v += __shfl_xor_sync(0xffffffffu, v, 8);
            v += __shfl_xor_sync(0xffffffffu, v, 4);
            v += __shfl_xor_sync(0xffffffffu, v, 2);
            v += __shfl_xor_sync(0xffffffffu, v, 1);
            if (l == 0) s_red[w][e] = v;
        }
        #pragma unroll
        for (int r = 0; r < 6; r++) atomicAdd(&s_cnt[idxs[r]], 1.0f);
    }
    __syncthreads();
    if (tid < 64) {
        float a = s_red[0][tid] + s_red[1][tid] + s_red[2][tid] + s_red[3][tid];
        int b = (tile * BM) / S_SEQ;
        atomicAdd(&g_ssum[b][tid], a);
        atomicAdd(&g_cnt [b][tid], s_cnt[tid]);
    }
}

// aux_loss = ALPHA * mean_b sum_e (cnt/(S*K/E)) * (ssum/S)   — R3 verbatim
__global__ void aux_kernel(float* __restrict__ out) {
    __shared__ float red[256];
    int tid = threadIdx.x;
    red[tid] = ((const float*)g_cnt)[tid] * ((const float*)g_ssum)[tid];
    __syncthreads();
    for (int s2 = 128; s2 > 0; s2 >>= 1) {
        if (tid < s2) red[tid] += red[tid + s2];
        __syncthreads();
    }
    if (tid == 0)
        out[2 * T_TOK * TOPK] = red[0] * (0.001f / (4.0f * 384.0f * 4096.0f));
}

extern "C" void kernel_launch(void* const* d_in, const int* in_sizes, int n_in,
                              void* d_out, int out_size) {
    const float* X = (const float*)d_in[0];   // [4,4096,4096] fp32
    const float* W = (const float*)d_in[1];   // [64,4096] fp32
    float* out = (float*)d_out;

    cudaFuncSetAttribute(moe_kernel, cudaFuncAttributeMaxDynamicSharedMemorySize, DYN);
    prep_kernel<<<64, 256>>>(W);
    moe_kernel<<<T_TOK / BM, NT, DYN>>>(X, out);
    aux_kernel<<<1, 256>>>(out);
}

// round 17
// speedup vs baseline: 1.9647x; 1.1240x over previous
#include <cuda_runtime.h>
#include <cuda_fp16.h>
#include <cstdint>

typedef unsigned long long ull;

constexpr int T_TOK = 16384;
constexpr int H_DIM = 4096;
constexpr int N_E   = 64;
constexpr int TOPK  = 6;
constexpr int S_SEQ = 4096;

constexpr int BM     = 128;           // tokens per CTA
constexpr int BK     = 128;           // fp32 K per stage
constexpr int NSTAGE = H_DIM / BK;    // 32
constexpr int NT     = 256;           // 8 warps

constexpr int XBYTES = BM * BK * 4;       // 65536
constexpr int WBYTES = N_E * BK * 2 * 2;  // 32768 (2 splits, f16)
constexpr int STAGE  = XBYTES + WBYTES;   // 98304
constexpr int DYN    = 2 * STAGE;         // 196608 < 227KB cap

// static device scratch
__device__ __half g_W1[N_E * H_DIM];
__device__ __half g_W2[N_E * H_DIM];
__device__ float  g_ssum[4][64];
__device__ float  g_cnt [4][64];

// ---------------------------------------------------------------------------
__device__ __forceinline__ uint32_t smem_u32(const void* p) {
    return (uint32_t)__cvta_generic_to_shared(p);
}
__device__ __forceinline__ void cp16(uint32_t dst, const void* src) {
    asm volatile("cp.async.cg.shared.global [%0], [%1], 16;" :: "r"(dst), "l"(src));
}
__device__ __forceinline__ void ldsm4(uint32_t& r0, uint32_t& r1, uint32_t& r2,
                                      uint32_t& r3, uint32_t a) {
    asm volatile("ldmatrix.sync.aligned.m8n8.x4.shared.b16 {%0,%1,%2,%3}, [%4];"
                 : "=r"(r0), "=r"(r1), "=r"(r2), "=r"(r3) : "r"(a));
}
__device__ __forceinline__ void mma16816(float* c, const uint32_t* a,
                                         uint32_t b0, uint32_t b1) {
    asm volatile(
        "mma.sync.aligned.m16n8k16.row.col.f32.f16.f16.f32 "
        "{%0,%1,%2,%3}, {%4,%5,%6,%7}, {%8,%9}, {%0,%1,%2,%3};"
        : "+f"(c[0]), "+f"(c[1]), "+f"(c[2]), "+f"(c[3])
        : "r"(a[0]), "r"(a[1]), "r"(a[2]), "r"(a[3]), "r"(b0), "r"(b1));
}
__device__ __forceinline__ void split32(float2 v, uint32_t& hi, uint32_t& lo) {
    v.x *= 32.f; v.y *= 32.f;
    __half2 h = __float22half2_rn(v);
    float2 b = __half22float2(h);
    __half2 L = __float22half2_rn(make_float2(v.x - b.x, v.y - b.y));
    hi = *(uint32_t*)&h;
    lo = *(uint32_t*)&L;
}
// X smem: row r (0..127) x 128 floats (512B = 32 units), swizzled within 8-unit groups
__device__ __forceinline__ float2 ldx(const float* xb, int r, int k) {
    int u  = k >> 2;                                  // 0..31
    int up = (u & 24) | ((u ^ (r & 7)) & 7);
    return *(const float2*)(xb + r * 128 + up * 4 + (k & 3));
}

// ---------------------------------------------------------------------------
// Prep: split W into 2 f16 terms (scaled by 1024), zero aux accumulators
// ---------------------------------------------------------------------------
__global__ __launch_bounds__(256) void prep_kernel(const float* __restrict__ W) {
    int idx = blockIdx.x * 256 + threadIdx.x;
    if (blockIdx.x == 0) {
        ((float*)g_ssum)[threadIdx.x] = 0.f;
        ((float*)g_cnt )[threadIdx.x] = 0.f;
    }
    #pragma unroll
    for (int r = 0; r < 4; r++) {
        int i = idx + r * 16384;              // float4 index, 65536 total
        float4 v = ((const float4*)W)[i];
        float a0 = v.x * 1024.f, a1 = v.y * 1024.f, a2 = v.z * 1024.f, a3 = v.w * 1024.f;
        __half2 h01 = __float22half2_rn(make_float2(a0, a1));
        __half2 h23 = __float22half2_rn(make_float2(a2, a3));
        float2 b01 = __half22float2(h01);
        float2 b23 = __half22float2(h23);
        __half2 l01 = __float22half2_rn(make_float2(a0 - b01.x, a1 - b01.y));
        __half2 l23 = __float22half2_rn(make_float2(a2 - b23.x, a3 - b23.y));
        uint2 hw, lw;
        hw.x = *(uint32_t*)&h01; hw.y = *(uint32_t*)&h23;
        lw.x = *(uint32_t*)&l01; lw.y = *(uint32_t*)&l23;
        ((uint2*)g_W1)[i] = hw;
        ((uint2*)g_W2)[i] = lw;
    }
}

// ---------------------------------------------------------------------------
// Fused GEMM (R3 mapping, BK=128 stages) + gating epilogue
// ---------------------------------------------------------------------------
__global__ __launch_bounds__(NT, 1) void moe_kernel(const float* __restrict__ X,
                                                    float* __restrict__ out) {
    extern __shared__ char dsm[];
    __shared__ float s_red[4][64];
    __shared__ float s_cnt[64];

    const int tid  = threadIdx.x;
    const int w    = tid >> 5;
    const int l    = tid & 31;
    const int tile = blockIdx.x;
    const float* Xt = X + (size_t)tile * BM * H_DIM;

    if (tid < 64) s_cnt[tid] = 0.f;

    // stage loader (cp.async): X 4096 chunks, W 2048 chunks of 16B
    auto load_stage = [&](int s) {
        const int k0 = s * BK;
        const uint32_t xb = smem_u32(dsm) + (s & 1) * STAGE;
        const uint32_t wb = xb + XBYTES;
        #pragma unroll
        for (int i = 0; i < 16; i++) {                // 128 rows x 32 units
            int ch = tid + i * NT;
            int r = ch >> 5, u = ch & 31;
            int up = (u & 24) | ((u ^ (r & 7)) & 7);
            cp16(xb + r * 512 + up * 16, Xt + (size_t)r * H_DIM + k0 + u * 4);
        }
        #pragma unroll
        for (int i = 0; i < 8; i++) {                 // 64 experts x 32 units
            int ch = tid + i * NT;
            int e = ch >> 5, u = ch & 31;
            int split = u >> 4, kk = u & 15;          // units 0..15 hi, 16..31 lo
            int up = (u & 24) | ((u ^ (e & 7)) & 7);
            const __half* src = (split ? g_W2 : g_W1) + e * H_DIM + k0 + kk * 8;
            cp16(wb + e * 512 + up * 16, src);
        }
        asm volatile("cp.async.commit_group;");
    };

    float acc[8][4];
    #pragma unroll
    for (int i = 0; i < 8; i++)
        #pragma unroll
        for (int j = 0; j < 4; j++) acc[i][j] = 0.f;

    // R3 lane constants: warp = 16 tokens x 64 experts
    const int t8     = l >> 3;
    const int e_base = (t8 >> 1) * 8 + (l & 7);
    const int koff   = t8 & 1;
    const int c7     = e_base & 7;

    load_stage(0);

    for (int s = 0; s < NSTAGE; s++) {
        if (s + 1 < NSTAGE) {
            load_stage(s + 1);
            asm volatile("cp.async.wait_group 1;");
        } else {
            asm volatile("cp.async.wait_group 0;");
        }
        __syncthreads();

        const char* sb = dsm + (s & 1) * STAGE;
        const float* xb = (const float*)sb;
        const uint32_t wbe = smem_u32(sb + XBYTES) + e_base * 512;
        const int r0 = w * 16 + (l >> 2);
        const int r1 = r0 + 8;

        #pragma unroll
        for (int c16 = 0; c16 < 8; c16++) {
            const int kA = c16 * 16 + (l & 3) * 2;
            uint32_t ahi[4], alo[4];
            split32(ldx(xb, r0, kA),     ahi[0], alo[0]);
            split32(ldx(xb, r1, kA),     ahi[1], alo[1]);
            split32(ldx(xb, r0, kA + 8), ahi[2], alo[2]);
            split32(ldx(xb, r1, kA + 8), ahi[3], alo[3]);

            const int u0  = c16 * 2 + koff;                  // 0..15
            const int uph = (u0 & 8) | ((u0 ^ c7) & 7);      // swizzle in 8-unit group
            #pragma unroll
            for (int pe = 0; pe < 4; pe++) {
                uint32_t ah = wbe + pe * 8192 + uph * 16;    // hi units 0..15
                uint32_t bh0, bh1, bh2, bh3, bl0, bl1, bl2, bl3;
                ldsm4(bh0, bh1, bh2, bh3, ah);
                ldsm4(bl0, bl1, bl2, bl3, ah + 256);         // lo units 16..31
                mma16816(acc[2 * pe],     ahi, bh0, bh1);
                mma16816(acc[2 * pe],     ahi, bl0, bl1);
                mma16816(acc[2 * pe],     alo, bh0, bh1);
                mma16816(acc[2 * pe + 1], ahi, bh2, bh3);
                mma16816(acc[2 * pe + 1], ahi, bl2, bl3);
                mma16816(acc[2 * pe + 1], alo, bh2, bh3);
            }
        }
        __syncthreads();
    }

    // ---------------- epilogue: transpose scores to smem ----------------
    float* S = (float*)dsm;               // [128][65]
    {
        const int r0 = w * 16 + (l >> 2);
        const int c0 = (l & 3) * 2;
        constexpr float INV = 1.0f / 32768.0f;
        #pragma unroll
        for (int eb = 0; eb < 8; eb++) {
            S[r0 * 65 + eb * 8 + c0]           = acc[eb][0] * INV;
            S[r0 * 65 + eb * 8 + c0 + 1]       = acc[eb][1] * INV;
            S[(r0 + 8) * 65 + eb * 8 + c0]     = acc[eb][2] * INV;
            S[(r0 + 8) * 65 + eb * 8 + c0 + 1] = acc[eb][3] * INV;
        }
    }
    __syncthreads();

    if (tid < 128) {
        float sc[64];
        #pragma unroll
        for (int e = 0; e < 64; e++) sc[e] = S[tid * 65 + e];

        // softmax
        float m = sc[0];
        #pragma unroll
        for (int e = 1; e < 64; e++) m = fmaxf(m, sc[e]);
        float ssum = 0.f;
        #pragma unroll
        for (int e = 0; e < 64; e++) { sc[e] = expf(sc[e] - m); ssum += sc[e]; }
        float inv = 1.0f / ssum;
        #pragma unroll
        for (int e = 0; e < 64; e++) sc[e] *= inv;

        // group maxima
        float gm[8];
        #pragma unroll
        for (int g = 0; g < 8; g++) {
            float a = sc[g * 8];
            #pragma unroll
            for (int j = 1; j < 8; j++) a = fmaxf(a, sc[g * 8 + j]);
            gm[g] = a;
        }
        // top-3 groups
        unsigned keep = 0;
        #pragma unroll
        for (int r = 0; r < 3; r++) {
            float bv = -1.f; int bi = 0;
            #pragma unroll
            for (int g = 0; g < 8; g++) {
                bool ok = !((keep >> g) & 1) && (gm[g] > bv);
                if (ok) { bv = gm[g]; bi = g; }
            }
            keep |= 1u << bi;
        }
        // top-6 experts in kept groups
        ull picked = 0;
        float wsum = 0.f;
        int idxs[6]; float vals[6];
        #pragma unroll
        for (int r = 0; r < 6; r++) {
            float bv = -1.f; int bi = 0;
            #pragma unroll
            for (int e = 0; e < 64; e++) {
                bool ok = ((keep >> (e >> 3)) & 1) && !((picked >> e) & 1) && (sc[e] > bv);
                if (ok) { bv = sc[e]; bi = e; }
            }
            picked |= 1ull << bi;
            idxs[r] = bi; vals[r] = bv; wsum += bv;
        }
        float inv2 = 1.0f / (wsum + 1e-20f);

        const int t = tile * BM + tid;
        #pragma unroll
        for (int r = 0; r < 6; r++) {
            out[t * TOPK + r]                = (float)idxs[r];
            out[T_TOK * TOPK + t * TOPK + r] = vals[r] * inv2;
        }

        // aux accumulators
        #pragma unroll
        for (int e = 0; e < 64; e++) {
            float v = sc[e];
            v += __shfl_xor_sync(0xffffffffu, v, 16);
            v += __shfl_xor_sync(0xffffffffu, v, 8);
            v += __shfl_xor_sync(0xffffffffu, v, 4);
            v += __shfl_xor_sync(0xffffffffu, v, 2);
            v += __shfl_xor_sync(0xffffffffu, v, 1);
            if (l == 0) s_red[w][e] = v;
        }
        #pragma unroll
        for (int r = 0; r < 6; r++) atomicAdd(&s_cnt[idxs[r]], 1.0f);
    }
    __syncthreads();
    if (tid < 64) {
        float a = s_red[0][tid] + s_red[1][tid] + s_red[2][tid] + s_red[3][tid];
        int b = (tile * BM) / S_SEQ;
        atomicAdd(&g_ssum[b][tid], a);
        atomicAdd(&g_cnt [b][tid], s_cnt[tid]);
    }
}

// aux_loss = ALPHA * mean_b sum_e (cnt/(S*K/E)) * (ssum/S)
__global__ void aux_kernel(float* __restrict__ out) {
    __shared__ float red[256];
    int tid = threadIdx.x;
    red[tid] = ((const float*)g_cnt)[tid] * ((const float*)g_ssum)[tid];
    __syncthreads();
    for (int s2 = 128; s2 > 0; s2 >>= 1) {
        if (tid < s2) red[tid] += red[tid + s2];
        __syncthreads();
    }
    if (tid == 0)
        out[2 * T_TOK * TOPK] = red[0] * (0.001f / (4.0f * 384.0f * 4096.0f));
}

extern "C" void kernel_launch(void* const* d_in, const int* in_sizes, int n_in,
                              void* d_out, int out_size) {
    const float* X = (const float*)d_in[0];   // [4,4096,4096] fp32
    const float* W = (const float*)d_in[1];   // [64,4096] fp32
    float* out = (float*)d_out;

    cudaFuncSetAttribute(moe_kernel, cudaFuncAttributeMaxDynamicSharedMemorySize, DYN);
    prep_kernel<<<64, 256>>>(W);
    moe_kernel<<<T_TOK / BM, NT, DYN>>>(X, out);
    aux_kernel<<<1, 256>>>(out);
}